// round 10
// baseline (speedup 1.0000x reference)
#include <cuda_runtime.h>
#include <cuda_fp16.h>
#include <math.h>

#define NB 4
#define NS 2048
#define ND 1024
#define NH 16
#define NDK 64
#define NM (NB*NS)

// Scratch (device globals: allocation-free rule) — fp16 pipeline
__device__ __half g_xh[(size_t)NM*ND];
__device__ __half g_wqh[(size_t)ND*ND];
__device__ __half g_wkh[(size_t)ND*ND];
__device__ __half g_wvh[(size_t)ND*ND];
__device__ __half g_woh[(size_t)ND*ND];
__device__ __half g_q[(size_t)NM*ND];
__device__ __half g_k[(size_t)NM*ND];
__device__ __half g_v[(size_t)NM*ND];
__device__ __half g_oh[(size_t)NM*ND];
__device__ float  g_cos[NS*(NDK/2)];
__device__ float  g_sin[NS*(NDK/2)];

// ---------------------------------------------------------------------------
// RoPE cos/sin table
// ---------------------------------------------------------------------------
__global__ void rope_table_kernel() {
    int idx = blockIdx.x * blockDim.x + threadIdx.x;
    if (idx >= NS * 32) return;
    int s = idx >> 5;
    int i = idx & 31;
    double freq = exp(-((double)(2 * i) / (double)NDK) * log(10000.0));
    double ang = (double)s * freq;
    g_cos[idx] = (float)cos(ang);
    g_sin[idx] = (float)sin(ang);
}

// ---------------------------------------------------------------------------
// helpers
// ---------------------------------------------------------------------------
__device__ __forceinline__ uint4 pack8h(float4 lo, float4 hi) {
    __half2 h0 = __floats2half2_rn(lo.x, lo.y);
    __half2 h1 = __floats2half2_rn(lo.z, lo.w);
    __half2 h2 = __floats2half2_rn(hi.x, hi.y);
    __half2 h3 = __floats2half2_rn(hi.z, hi.w);
    return make_uint4(*reinterpret_cast<unsigned*>(&h0),
                      *reinterpret_cast<unsigned*>(&h1),
                      *reinterpret_cast<unsigned*>(&h2),
                      *reinterpret_cast<unsigned*>(&h3));
}

__global__ void cvt_h_kernel(const float* __restrict__ src, __half* __restrict__ dst, int n) {
    int i = (blockIdx.x * blockDim.x + threadIdx.x) << 3;
    if (i >= n) return;
    float4 lo = *(const float4*)(src + i);
    float4 hi = *(const float4*)(src + i + 4);
    *(uint4*)(dst + i) = pack8h(lo, hi);
}

__device__ __forceinline__ unsigned smem_u32(const void* p) {
    return (unsigned)__cvta_generic_to_shared(p);
}

__device__ __forceinline__ void cp_async16(void* smem, const void* gmem) {
    asm volatile("cp.async.cg.shared.global [%0], [%1], 16;"
                 :: "r"(smem_u32(smem)), "l"(gmem));
}
__device__ __forceinline__ void cp_commit() { asm volatile("cp.async.commit_group;"); }
__device__ __forceinline__ void cp_wait0()  { asm volatile("cp.async.wait_group 0;"); }

__device__ __forceinline__ void ldsm_x4(unsigned& r0, unsigned& r1,
                                        unsigned& r2, unsigned& r3, unsigned a) {
    asm volatile("ldmatrix.sync.aligned.m8n8.x4.shared.b16 {%0,%1,%2,%3}, [%4];"
                 : "=r"(r0), "=r"(r1), "=r"(r2), "=r"(r3) : "r"(a));
}

__device__ __forceinline__ void ldsm_x4_t(unsigned& r0, unsigned& r1,
                                          unsigned& r2, unsigned& r3, unsigned a) {
    asm volatile("ldmatrix.sync.aligned.m8n8.x4.trans.shared.b16 {%0,%1,%2,%3}, [%4];"
                 : "=r"(r0), "=r"(r1), "=r"(r2), "=r"(r3) : "r"(a));
}

__device__ __forceinline__ void mma_f16(float* c, const unsigned* a, const unsigned* b) {
    asm volatile("mma.sync.aligned.m16n8k16.row.col.f32.f16.f16.f32 "
                 "{%0,%1,%2,%3}, {%4,%5,%6,%7}, {%8,%9}, {%0,%1,%2,%3};"
                 : "+f"(c[0]), "+f"(c[1]), "+f"(c[2]), "+f"(c[3])
                 : "r"(a[0]), "r"(a[1]), "r"(a[2]), "r"(a[3]),
                   "r"(b[0]), "r"(b[1]));
}

__device__ __forceinline__ void st2(float* p, float a, float b) {
    *(float2*)p = make_float2(a, b);
}
__device__ __forceinline__ void st2(__half* p, float a, float b) {
    *(__half2*)p = __floats2half2_rn(a, b);
}

// ---------------------------------------------------------------------------
// Pipelined tensor-core NT GEMM (fp16 in, fp32 accum).
// BM=BN=128, BK=64, 2-stage cp.async double buffer (73.7KB dynamic SMEM).
// 8 warps; warp tile 64x32; mma m16n8k16 via ldmatrix.x4; stride 72 halves.
// blockIdx.z selects (W, C) pair; z < NROPE => fused interleaved RoPE.
// ---------------------------------------------------------------------------
#define GKS 72
#define GTILE_H (128 * GKS)
#define GEMM_SMEM (4 * GTILE_H * (int)sizeof(__half))

template<int NROPE, typename TOUT>
__global__ __launch_bounds__(256) void gemm_tc(
    const __half* __restrict__ A,
    const __half* __restrict__ Wa, const __half* __restrict__ Wb, const __half* __restrict__ Wc,
    TOUT* __restrict__ Ca, TOUT* __restrict__ Cb, TOUT* __restrict__ Cc)
{
    const __half* Wt = (blockIdx.z == 0) ? Wa : (blockIdx.z == 1 ? Wb : Wc);
    TOUT*         C  = (blockIdx.z == 0) ? Ca : (blockIdx.z == 1 ? Cb : Cc);
    const int rope   = (int)blockIdx.z < NROPE;

    extern __shared__ __half hsm[];
    __half* AsB[2] = { hsm,               hsm + GTILE_H     };
    __half* BsB[2] = { hsm + 2 * GTILE_H, hsm + 3 * GTILE_H };

    const int tid  = threadIdx.x;
    const int warp = tid >> 5;
    const int lane = tid & 31;
    const int wm   = warp >> 2;
    const int wn   = warp & 3;
    const int gid  = lane >> 2;
    const int tig  = lane & 3;
    const int bm   = blockIdx.y * 128;
    const int bn   = blockIdx.x * 128;

    // loader: 2 threads/row, 32 halves (64B = 4 x cp.async16) each
    const int lr = tid >> 1;
    const int lc = (tid & 1) << 5;
    const __half* Ap = A  + (size_t)(bm + lr) * ND + lc;
    const __half* Wp = Wt + (size_t)(bn + lr) * ND + lc;

    // ldmatrix lane geometry
    const int ra   = (lane & 7) + ((lane >> 3) & 1) * 8;
    const int kaa  = ((lane >> 4) & 1) * 8;
    const int rb   = lane & 7;
    const int kbb  = ((lane >> 3) & 1) * 8;
    const int nbb  = ((lane >> 4) & 1) * 8;

    float acc[4][4][4];
    #pragma unroll
    for (int mt = 0; mt < 4; mt++)
        #pragma unroll
        for (int nt = 0; nt < 4; nt++)
            #pragma unroll
            for (int c = 0; c < 4; c++) acc[mt][nt][c] = 0.0f;

    // prologue: stage k-tile 0
    #pragma unroll
    for (int j = 0; j < 4; j++) {
        cp_async16(AsB[0] + lr * GKS + lc + j * 8, Ap + j * 8);
        cp_async16(BsB[0] + lr * GKS + lc + j * 8, Wp + j * 8);
    }
    cp_commit();

    for (int t = 0; t < 16; t++) {
        const int cur = t & 1;
        cp_wait0();
        __syncthreads();

        if (t < 15) {
            const int nxt = cur ^ 1;
            const int k1 = (t + 1) * 64;
            #pragma unroll
            for (int j = 0; j < 4; j++) {
                cp_async16(AsB[nxt] + lr * GKS + lc + j * 8, Ap + k1 + j * 8);
                cp_async16(BsB[nxt] + lr * GKS + lc + j * 8, Wp + k1 + j * 8);
            }
            cp_commit();
        }

        const __half* as = AsB[cur];
        const __half* bs = BsB[cur];
        #pragma unroll
        for (int ks = 0; ks < 64; ks += 16) {
            unsigned af[4][4], bf[4][2];
            #pragma unroll
            for (int mt = 0; mt < 4; mt++) {
                unsigned a = smem_u32(&as[(wm * 64 + mt * 16 + ra) * GKS + ks + kaa]);
                ldsm_x4(af[mt][0], af[mt][1], af[mt][2], af[mt][3], a);
            }
            #pragma unroll
            for (int ntp = 0; ntp < 4; ntp += 2) {
                unsigned a = smem_u32(&bs[(wn * 32 + ntp * 8 + rb + nbb) * GKS + ks + kbb]);
                ldsm_x4(bf[ntp][0], bf[ntp][1], bf[ntp + 1][0], bf[ntp + 1][1], a);
            }
            #pragma unroll
            for (int mt = 0; mt < 4; mt++)
                #pragma unroll
                for (int nt = 0; nt < 4; nt++)
                    mma_f16(acc[mt][nt], af[mt], bf[nt]);
        }
    }

    __syncthreads();

    #pragma unroll
    for (int mt = 0; mt < 4; mt++) {
        int m0 = bm + wm * 64 + mt * 16 + gid;
        #pragma unroll
        for (int nt = 0; nt < 4; nt++) {
            int n = bn + wn * 32 + nt * 8 + 2 * tig;
            float c0 = acc[mt][nt][0], c1 = acc[mt][nt][1];
            float c2 = acc[mt][nt][2], c3 = acc[mt][nt][3];
            if (rope) {
                int ip = (n & 63) >> 1;
                int s0 = m0 & (NS - 1);
                int s1 = (m0 + 8) & (NS - 1);
                float ca = g_cos[s0 * 32 + ip], sa = g_sin[s0 * 32 + ip];
                float cb = g_cos[s1 * 32 + ip], sb = g_sin[s1 * 32 + ip];
                float t0 = c0 * ca - c1 * sa;
                float t1 = c0 * sa + c1 * ca;
                float t2 = c2 * cb - c3 * sb;
                float t3 = c2 * sb + c3 * cb;
                c0 = t0; c1 = t1; c2 = t2; c3 = t3;
            }
            st2(C + (size_t)m0 * ND + n,       c0, c1);
            st2(C + (size_t)(m0 + 8) * ND + n, c2, c3);
        }
    }
}

// ---------------------------------------------------------------------------
// Pipelined tensor-core causal flash attention (fp16 mma + ldmatrix).
// grid = (S/128, H, B), 256 threads (8 warps x 16 q-rows), 64-key tiles.
// K/V double-buffered via cp.async; Ks/Vs natural [kv][d], stride 72.
// ---------------------------------------------------------------------------
#define FST 72
#define FTILE_H (64 * FST)
#define FA_SMEM ((4 * FTILE_H + 128 * FST) * (int)sizeof(__half))

__global__ __launch_bounds__(256, 2) void flash_tc_kernel() {
    extern __shared__ __half fsm[];
    __half* KsB[2] = { fsm,               fsm + FTILE_H     };
    __half* VsB[2] = { fsm + 2 * FTILE_H, fsm + 3 * FTILE_H };
    __half* Ps     = fsm + 4 * FTILE_H;

    const int tid  = threadIdx.x;
    const int warp = tid >> 5;
    const int lane = tid & 31;
    const int gid  = lane >> 2;
    const int tig  = lane & 3;
    const int q0   = blockIdx.x * 128;
    const int h    = blockIdx.y;
    const int b    = blockIdx.z;
    const size_t base = (size_t)(b * NS) * ND + (size_t)h * NDK;

    // ldmatrix lane geometry
    const int roff = (lane & 7) + ((lane >> 3) & 1) * 8;
    const int koff = ((lane >> 4) & 1) * 8;
    const int rk   = lane & 7;
    const int kofl = ((lane >> 3) & 1) * 8;
    const int nofl = ((lane >> 4) & 1) * 8;
    const int rv   = (lane & 7) + ((lane >> 3) & 1) * 8;
    const int dofl = ((lane >> 4) & 1) * 8;

    // K/V loader: 4 threads/row, 16 halves (32B = 2 x cp.async16) each
    const int klr = tid >> 2;
    const int klc = (tid & 3) << 4;
    const __half* Kp = g_k + base + (size_t)klr * ND + klc;
    const __half* Vp = g_v + base + (size_t)klr * ND + klc;

    // prologue: stage K/V tile 0 asynchronously
    #pragma unroll
    for (int j = 0; j < 2; j++) {
        cp_async16(KsB[0] + klr * FST + klc + j * 8, Kp + j * 8);
        cp_async16(VsB[0] + klr * FST + klc + j * 8, Vp + j * 8);
    }
    cp_commit();

    // stage Q (scaled by 1/8) into Ps — overlaps with K/V tile-0 copy
    const __half2 qscale = __float2half2_rn(0.125f);
    for (int l = tid; l < 128 * 8; l += 256) {
        int r = l >> 3;
        int c = (l & 7) << 3;
        uint4 v = *(const uint4*)(g_q + base + (size_t)(q0 + r) * ND + c);
        __half2* hp = (__half2*)&v;
        hp[0] = __hmul2(hp[0], qscale);
        hp[1] = __hmul2(hp[1], qscale);
        hp[2] = __hmul2(hp[2], qscale);
        hp[3] = __hmul2(hp[3], qscale);
        *(uint4*)(&Ps[r * FST + c]) = v;
    }
    __syncthreads();

    unsigned qf[4][4];
    #pragma unroll
    for (int ks = 0; ks < 4; ks++) {
        unsigned a = smem_u32(&Ps[(warp * 16 + roff) * FST + ks * 16 + koff]);
        ldsm_x4(qf[ks][0], qf[ks][1], qf[ks][2], qf[ks][3], a);
    }

    float o[8][4];
    #pragma unroll
    for (int nt = 0; nt < 8; nt++)
        #pragma unroll
        for (int c = 0; c < 4; c++) o[nt][c] = 0.0f;
    float m_a = -1e30f, m_b = -1e30f, l_a = 0.0f, l_b = 0.0f;
    const int row_a = q0 + warp * 16 + gid;
    const int row_b = row_a + 8;
    const int nk = 2 * blockIdx.x + 2;

    for (int kt = 0; kt < nk; kt++) {
        const int cur = kt & 1;
        cp_wait0();
        __syncthreads();

        if (kt + 1 < nk) {
            const int nxt = cur ^ 1;
            const size_t off = (size_t)(kt + 1) * 64 * ND;
            #pragma unroll
            for (int j = 0; j < 2; j++) {
                cp_async16(KsB[nxt] + klr * FST + klc + j * 8, Kp + off + j * 8);
                cp_async16(VsB[nxt] + klr * FST + klc + j * 8, Vp + off + j * 8);
            }
            cp_commit();
        }

        const int k0 = kt * 64;
        if (k0 <= q0 + warp * 16 + 15) {
            const __half* Ks = KsB[cur];
            const __half* Vs = VsB[cur];

            // S = Q K^T
            float s[8][4];
            #pragma unroll
            for (int nt = 0; nt < 8; nt++)
                #pragma unroll
                for (int c = 0; c < 4; c++) s[nt][c] = 0.0f;

            #pragma unroll
            for (int ks = 0; ks < 4; ks++) {
                unsigned bf[8][2];
                #pragma unroll
                for (int ntp = 0; ntp < 8; ntp += 2) {
                    unsigned a = smem_u32(&Ks[(ntp * 8 + rk + nofl) * FST + ks * 16 + kofl]);
                    ldsm_x4(bf[ntp][0], bf[ntp][1], bf[ntp + 1][0], bf[ntp + 1][1], a);
                }
                #pragma unroll
                for (int nt = 0; nt < 8; nt++)
                    mma_f16(s[nt], qf[ks], bf[nt]);
            }

            // causal mask
            if (k0 + 63 > q0 + warp * 16) {
                #pragma unroll
                for (int nt = 0; nt < 8; nt++) {
                    int kg = k0 + nt * 8 + 2 * tig;
                    if (kg     > row_a) s[nt][0] = -1e30f;
                    if (kg + 1 > row_a) s[nt][1] = -1e30f;
                    if (kg     > row_b) s[nt][2] = -1e30f;
                    if (kg + 1 > row_b) s[nt][3] = -1e30f;
                }
            }

            // online softmax
            float mx_a = -1e30f, mx_b = -1e30f;
            #pragma unroll
            for (int nt = 0; nt < 8; nt++) {
                mx_a = fmaxf(mx_a, fmaxf(s[nt][0], s[nt][1]));
                mx_b = fmaxf(mx_b, fmaxf(s[nt][2], s[nt][3]));
            }
            mx_a = fmaxf(mx_a, __shfl_xor_sync(0xffffffffu, mx_a, 1));
            mx_a = fmaxf(mx_a, __shfl_xor_sync(0xffffffffu, mx_a, 2));
            mx_b = fmaxf(mx_b, __shfl_xor_sync(0xffffffffu, mx_b, 1));
            mx_b = fmaxf(mx_b, __shfl_xor_sync(0xffffffffu, mx_b, 2));

            float mn_a = fmaxf(m_a, mx_a), mn_b = fmaxf(m_b, mx_b);
            float al_a = __expf(m_a - mn_a), al_b = __expf(m_b - mn_b);
            float rs_a = 0.0f, rs_b = 0.0f;
            #pragma unroll
            for (int nt = 0; nt < 8; nt++) {
                s[nt][0] = __expf(s[nt][0] - mn_a);
                s[nt][1] = __expf(s[nt][1] - mn_a);
                s[nt][2] = __expf(s[nt][2] - mn_b);
                s[nt][3] = __expf(s[nt][3] - mn_b);
                rs_a += s[nt][0] + s[nt][1];
                rs_b += s[nt][2] + s[nt][3];
            }
            rs_a += __shfl_xor_sync(0xffffffffu, rs_a, 1);
            rs_a += __shfl_xor_sync(0xffffffffu, rs_a, 2);
            rs_b += __shfl_xor_sync(0xffffffffu, rs_b, 1);
            rs_b += __shfl_xor_sync(0xffffffffu, rs_b, 2);

            l_a = l_a * al_a + rs_a;
            l_b = l_b * al_b + rs_b;
            m_a = mn_a;
            m_b = mn_b;

            #pragma unroll
            for (int nt = 0; nt < 8; nt++) {
                o[nt][0] *= al_a; o[nt][1] *= al_a;
                o[nt][2] *= al_b; o[nt][3] *= al_b;
            }

            // P -> SMEM (fp16), own-warp rows only
            __half2* Pa = (__half2*)&Ps[(warp * 16 + gid) * FST];
            __half2* Pb = (__half2*)&Ps[(warp * 16 + gid + 8) * FST];
            #pragma unroll
            for (int nt = 0; nt < 8; nt++) {
                Pa[nt * 4 + tig] = __floats2half2_rn(s[nt][0], s[nt][1]);
                Pb[nt * 4 + tig] = __floats2half2_rn(s[nt][2], s[nt][3]);
            }
            __syncwarp();

            // O += P V   (V^T via ldmatrix.trans)
            #pragma unroll
            for (int ks = 0; ks < 4; ks++) {
                unsigned af[4];
                {
                    unsigned a = smem_u32(&Ps[(warp * 16 + roff) * FST + ks * 16 + koff]);
                    ldsm_x4(af[0], af[1], af[2], af[3], a);
                }
                unsigned vf[8][2];
                #pragma unroll
                for (int dtp = 0; dtp < 8; dtp += 2) {
                    unsigned a = smem_u32(&Vs[(ks * 16 + rv) * FST + dtp * 8 + dofl]);
                    ldsm_x4_t(vf[dtp][0], vf[dtp][1], vf[dtp + 1][0], vf[dtp + 1][1], a);
                }
                #pragma unroll
                for (int nt = 0; nt < 8; nt++)
                    mma_f16(o[nt], af, vf[nt]);
            }
        }
    }

    // normalize + write O (fp16)
    float ia = 1.0f / l_a, ib = 1.0f / l_b;
    #pragma unroll
    for (int nt = 0; nt < 8; nt++) {
        int d = nt * 8 + 2 * tig;
        *(__half2*)(g_oh + base + (size_t)row_a * ND + d) =
            __floats2half2_rn(o[nt][0] * ia, o[nt][1] * ia);
        *(__half2*)(g_oh + base + (size_t)row_b * ND + d) =
            __floats2half2_rn(o[nt][2] * ib, o[nt][3] * ib);
    }
}

// ---------------------------------------------------------------------------
extern "C" void kernel_launch(void* const* d_in, const int* in_sizes, int n_in,
                              void* d_out, int out_size) {
    const float* x  = (const float*)d_in[0];
    // d_in[1] = mask (bool tril) -- causality is hardcoded
    const float* wq = (const float*)d_in[2];
    const float* wk = (const float*)d_in[3];
    const float* wv = (const float*)d_in[4];
    const float* wo = (const float*)d_in[5];
    float* out = (float*)d_out;

    void *pxh, *pwq, *pwk, *pwv, *pwo, *pq, *pk, *pv, *poh;
    cudaGetSymbolAddress(&pxh, g_xh);
    cudaGetSymbolAddress(&pwq, g_wqh);
    cudaGetSymbolAddress(&pwk, g_wkh);
    cudaGetSymbolAddress(&pwv, g_wvh);
    cudaGetSymbolAddress(&pwo, g_woh);
    cudaGetSymbolAddress(&pq, g_q);
    cudaGetSymbolAddress(&pk, g_k);
    cudaGetSymbolAddress(&pv, g_v);
    cudaGetSymbolAddress(&poh, g_oh);

    cudaFuncSetAttribute(gemm_tc<2, __half>,
                         cudaFuncAttributeMaxDynamicSharedMemorySize, GEMM_SMEM);
    cudaFuncSetAttribute(gemm_tc<0, float>,
                         cudaFuncAttributeMaxDynamicSharedMemorySize, GEMM_SMEM);
    cudaFuncSetAttribute(flash_tc_kernel,
                         cudaFuncAttributeMaxDynamicSharedMemorySize, FA_SMEM);

    rope_table_kernel<<<(NS * 32 + 255) / 256, 256>>>();

    // fp32 -> fp16 input/weight conversion
    cvt_h_kernel<<<(NM * ND / 8 + 255) / 256, 256>>>(x,  (__half*)pxh, NM * ND);
    cvt_h_kernel<<<(ND * ND / 8 + 255) / 256, 256>>>(wq, (__half*)pwq, ND * ND);
    cvt_h_kernel<<<(ND * ND / 8 + 255) / 256, 256>>>(wk, (__half*)pwk, ND * ND);
    cvt_h_kernel<<<(ND * ND / 8 + 255) / 256, 256>>>(wv, (__half*)pwv, ND * ND);
    cvt_h_kernel<<<(ND * ND / 8 + 255) / 256, 256>>>(wo, (__half*)pwo, ND * ND);

    // fused Q/K/V projections (z = 0,1,2; RoPE on z<2), fp16 outputs
    gemm_tc<2, __half><<<dim3(ND / 128, NM / 128, 3), 256, GEMM_SMEM>>>(
        (const __half*)pxh, (const __half*)pwq, (const __half*)pwk, (const __half*)pwv,
        (__half*)pq, (__half*)pk, (__half*)pv);

    flash_tc_kernel<<<dim3(NS / 128, NH, NB), 256, FA_SMEM>>>();

    // output projection: fp16 in, fp32 out
    gemm_tc<0, float><<<dim3(ND / 128, NM / 128, 1), 256, GEMM_SMEM>>>(
        (const __half*)poh, (const __half*)pwo, (const __half*)pwo, (const __half*)pwo,
        out, out, out);
}

// round 11
// speedup vs baseline: 1.6514x; 1.6514x over previous
#include <cuda_runtime.h>
#include <cuda_fp16.h>
#include <math.h>

#define NB 4
#define NS 2048
#define ND 1024
#define NH 16
#define NDK 64
#define NM (NB*NS)

// Scratch (device globals: allocation-free rule) — fp16 pipeline
__device__ __half g_xh[(size_t)NM*ND];
__device__ __half g_wqh[(size_t)ND*ND];
__device__ __half g_wkh[(size_t)ND*ND];
__device__ __half g_wvh[(size_t)ND*ND];
__device__ __half g_woh[(size_t)ND*ND];
__device__ __half g_q[(size_t)NM*ND];
__device__ __half g_k[(size_t)NM*ND];
__device__ __half g_v[(size_t)NM*ND];
__device__ __half g_oh[(size_t)NM*ND];
__device__ float  g_cos[NS*(NDK/2)];
__device__ float  g_sin[NS*(NDK/2)];

// ---------------------------------------------------------------------------
// RoPE cos/sin table
// ---------------------------------------------------------------------------
__global__ void rope_table_kernel() {
    int idx = blockIdx.x * blockDim.x + threadIdx.x;
    if (idx >= NS * 32) return;
    int s = idx >> 5;
    int i = idx & 31;
    double freq = exp(-((double)(2 * i) / (double)NDK) * log(10000.0));
    double ang = (double)s * freq;
    g_cos[idx] = (float)cos(ang);
    g_sin[idx] = (float)sin(ang);
}

// ---------------------------------------------------------------------------
// helpers
// ---------------------------------------------------------------------------
__device__ __forceinline__ uint4 pack8h(float4 lo, float4 hi) {
    __half2 h0 = __floats2half2_rn(lo.x, lo.y);
    __half2 h1 = __floats2half2_rn(lo.z, lo.w);
    __half2 h2 = __floats2half2_rn(hi.x, hi.y);
    __half2 h3 = __floats2half2_rn(hi.z, hi.w);
    return make_uint4(*reinterpret_cast<unsigned*>(&h0),
                      *reinterpret_cast<unsigned*>(&h1),
                      *reinterpret_cast<unsigned*>(&h2),
                      *reinterpret_cast<unsigned*>(&h3));
}

// fp32 -> fp16 convert for x (n multiple of 8)
__global__ void cvt_h_kernel(const float* __restrict__ src, __half* __restrict__ dst, int n) {
    int i = (blockIdx.x * blockDim.x + threadIdx.x) << 3;
    if (i >= n) return;
    float4 lo = *(const float4*)(src + i);
    float4 hi = *(const float4*)(src + i + 4);
    *(uint4*)(dst + i) = pack8h(lo, hi);
}

// fp32 -> fp16 convert for the 4 weight matrices (blockIdx.y selects)
__global__ void cvt_w_kernel(const float* __restrict__ w0, const float* __restrict__ w1,
                             const float* __restrict__ w2, const float* __restrict__ w3,
                             __half* __restrict__ d0, __half* __restrict__ d1,
                             __half* __restrict__ d2, __half* __restrict__ d3) {
    const float* src = (blockIdx.y == 0) ? w0 : (blockIdx.y == 1 ? w1 : (blockIdx.y == 2 ? w2 : w3));
    __half*      dst = (blockIdx.y == 0) ? d0 : (blockIdx.y == 1 ? d1 : (blockIdx.y == 2 ? d2 : d3));
    int i = (blockIdx.x * blockDim.x + threadIdx.x) << 3;
    if (i >= ND * ND) return;
    float4 lo = *(const float4*)(src + i);
    float4 hi = *(const float4*)(src + i + 4);
    *(uint4*)(dst + i) = pack8h(lo, hi);
}

__device__ __forceinline__ unsigned smem_u32(const void* p) {
    return (unsigned)__cvta_generic_to_shared(p);
}

__device__ __forceinline__ void ldsm_x4(unsigned& r0, unsigned& r1,
                                        unsigned& r2, unsigned& r3, unsigned a) {
    asm volatile("ldmatrix.sync.aligned.m8n8.x4.shared.b16 {%0,%1,%2,%3}, [%4];"
                 : "=r"(r0), "=r"(r1), "=r"(r2), "=r"(r3) : "r"(a));
}

__device__ __forceinline__ void ldsm_x4_t(unsigned& r0, unsigned& r1,
                                          unsigned& r2, unsigned& r3, unsigned a) {
    asm volatile("ldmatrix.sync.aligned.m8n8.x4.trans.shared.b16 {%0,%1,%2,%3}, [%4];"
                 : "=r"(r0), "=r"(r1), "=r"(r2), "=r"(r3) : "r"(a));
}

__device__ __forceinline__ void mma_f16(float* c, const unsigned* a, const unsigned* b) {
    asm volatile("mma.sync.aligned.m16n8k16.row.col.f32.f16.f16.f32 "
                 "{%0,%1,%2,%3}, {%4,%5,%6,%7}, {%8,%9}, {%0,%1,%2,%3};"
                 : "+f"(c[0]), "+f"(c[1]), "+f"(c[2]), "+f"(c[3])
                 : "r"(a[0]), "r"(a[1]), "r"(a[2]), "r"(a[3]),
                   "r"(b[0]), "r"(b[1]));
}

// output store: fp32 or fp16 destination
__device__ __forceinline__ void st2(float* p, float a, float b) {
    *(float2*)p = make_float2(a, b);
}
__device__ __forceinline__ void st2(__half* p, float a, float b) {
    *(__half2*)p = __floats2half2_rn(a, b);
}

// ---------------------------------------------------------------------------
// Tensor-core NT GEMM (fp16 in, fp32 accum): C[m,n] = sum_k A[m,k]*Wt[n,k].
// BM=BN=128, BK=32. 8 warps; warp tile 64x32; mma m16n8k16 via ldmatrix.x4.
// SMEM row stride 40 halves (80B): ldmatrix conflict-free.
// Register prefetch: tile t+1's LDG issued before tile t's compute, so the
// global-load latency overlaps the MMA phase. Single SMEM buffer, 2 bars/tile.
// blockIdx.z selects (W, C) pair; z < NROPE => fused interleaved RoPE.
// ---------------------------------------------------------------------------
#define GKS 40

template<int NROPE, typename TOUT>
__global__ __launch_bounds__(256) void gemm_tc(
    const __half* __restrict__ A,
    const __half* __restrict__ Wa, const __half* __restrict__ Wb, const __half* __restrict__ Wc,
    TOUT* __restrict__ Ca, TOUT* __restrict__ Cb, TOUT* __restrict__ Cc)
{
    const __half* Wt = (blockIdx.z == 0) ? Wa : (blockIdx.z == 1 ? Wb : Wc);
    TOUT*         C  = (blockIdx.z == 0) ? Ca : (blockIdx.z == 1 ? Cb : Cc);
    const int rope   = (int)blockIdx.z < NROPE;

    __shared__ __half As[128 * GKS];
    __shared__ __half Bs[128 * GKS];

    const int tid  = threadIdx.x;
    const int warp = tid >> 5;
    const int lane = tid & 31;
    const int wm   = warp >> 2;
    const int wn   = warp & 3;
    const int gid  = lane >> 2;
    const int tig  = lane & 3;
    const int bm   = blockIdx.y * 128;
    const int bn   = blockIdx.x * 128;

    // loader: 4 threads/row, 8 halves (one uint4) each; rows lr and lr+64
    const int lr = tid >> 2;
    const int lc = (tid & 3) << 3;
    const __half* Ap = A  + (size_t)(bm + lr) * ND + lc;
    const __half* Wp = Wt + (size_t)(bn + lr) * ND + lc;

    // ldmatrix lane geometry
    const int ra   = (lane & 7) + ((lane >> 3) & 1) * 8;
    const int kaa  = ((lane >> 4) & 1) * 8;
    const int rb   = lane & 7;
    const int kbb  = ((lane >> 3) & 1) * 8;
    const int nbb  = ((lane >> 4) & 1) * 8;

    float acc[4][4][4];
    #pragma unroll
    for (int mt = 0; mt < 4; mt++)
        #pragma unroll
        for (int nt = 0; nt < 4; nt++)
            #pragma unroll
            for (int c = 0; c < 4; c++) acc[mt][nt][c] = 0.0f;

    // prologue: load k-tile 0 into registers
    uint4 rga[2], rgb[2];
    #pragma unroll
    for (int p = 0; p < 2; p++) {
        rga[p] = *(const uint4*)(Ap + (size_t)p * 64 * ND);
        rgb[p] = *(const uint4*)(Wp + (size_t)p * 64 * ND);
    }

    for (int t = 0; t < 32; t++) {
        // store prefetched tile t into SMEM
        #pragma unroll
        for (int p = 0; p < 2; p++) {
            *(uint4*)(&As[(lr + p * 64) * GKS + lc]) = rga[p];
            *(uint4*)(&Bs[(lr + p * 64) * GKS + lc]) = rgb[p];
        }
        __syncthreads();

        // issue LDG for tile t+1 now — latency overlaps the compute below
        if (t < 31) {
            const int k1 = (t + 1) * 32;
            #pragma unroll
            for (int p = 0; p < 2; p++) {
                rga[p] = *(const uint4*)(Ap + (size_t)p * 64 * ND + k1);
                rgb[p] = *(const uint4*)(Wp + (size_t)p * 64 * ND + k1);
            }
        }

        #pragma unroll
        for (int ks = 0; ks < 32; ks += 16) {
            unsigned af[4][4], bf[4][2];
            #pragma unroll
            for (int mt = 0; mt < 4; mt++) {
                unsigned a = smem_u32(&As[(wm * 64 + mt * 16 + ra) * GKS + ks + kaa]);
                ldsm_x4(af[mt][0], af[mt][1], af[mt][2], af[mt][3], a);
            }
            #pragma unroll
            for (int ntp = 0; ntp < 4; ntp += 2) {
                unsigned a = smem_u32(&Bs[(wn * 32 + ntp * 8 + rb + nbb) * GKS + ks + kbb]);
                ldsm_x4(bf[ntp][0], bf[ntp][1], bf[ntp + 1][0], bf[ntp + 1][1], a);
            }
            #pragma unroll
            for (int mt = 0; mt < 4; mt++)
                #pragma unroll
                for (int nt = 0; nt < 4; nt++)
                    mma_f16(acc[mt][nt], af[mt], bf[nt]);
        }
        __syncthreads();
    }

    #pragma unroll
    for (int mt = 0; mt < 4; mt++) {
        int m0 = bm + wm * 64 + mt * 16 + gid;
        #pragma unroll
        for (int nt = 0; nt < 4; nt++) {
            int n = bn + wn * 32 + nt * 8 + 2 * tig;
            float c0 = acc[mt][nt][0], c1 = acc[mt][nt][1];
            float c2 = acc[mt][nt][2], c3 = acc[mt][nt][3];
            if (rope) {
                int ip = (n & 63) >> 1;
                int s0 = m0 & (NS - 1);
                int s1 = (m0 + 8) & (NS - 1);
                float ca = g_cos[s0 * 32 + ip], sa = g_sin[s0 * 32 + ip];
                float cb = g_cos[s1 * 32 + ip], sb = g_sin[s1 * 32 + ip];
                float t0 = c0 * ca - c1 * sa;
                float t1 = c0 * sa + c1 * ca;
                float t2 = c2 * cb - c3 * sb;
                float t3 = c2 * sb + c3 * cb;
                c0 = t0; c1 = t1; c2 = t2; c3 = t3;
            }
            st2(C + (size_t)m0 * ND + n,       c0, c1);
            st2(C + (size_t)(m0 + 8) * ND + n, c2, c3);
        }
    }
}

// ---------------------------------------------------------------------------
// Tensor-core causal flash attention (fp16 mma m16n8k16 + ldmatrix).
// grid = (S/128, H, B), 256 threads (8 warps x 16 q-rows), 64-key tiles.
// Q/K/V fp16 in gmem; O written fp16. Ks/Vs natural [kv][d], stride 72.
// [proven R8 version]
// ---------------------------------------------------------------------------
#define FST 72

__global__ __launch_bounds__(256, 2) void flash_tc_kernel() {
    __shared__ __half Ks[64 * FST];
    __shared__ __half Vs[64 * FST];
    __shared__ __half Ps[128 * FST];

    const int tid  = threadIdx.x;
    const int warp = tid >> 5;
    const int lane = tid & 31;
    const int gid  = lane >> 2;
    const int tig  = lane & 3;
    const int q0   = blockIdx.x * 128;
    const int h    = blockIdx.y;
    const int b    = blockIdx.z;
    const size_t base = (size_t)(b * NS) * ND + (size_t)h * NDK;

    // ldmatrix lane geometry
    const int roff = (lane & 7) + ((lane >> 3) & 1) * 8;
    const int koff = ((lane >> 4) & 1) * 8;
    const int rk   = lane & 7;
    const int kofl = ((lane >> 3) & 1) * 8;
    const int nofl = ((lane >> 4) & 1) * 8;
    const int rv   = (lane & 7) + ((lane >> 3) & 1) * 8;
    const int dofl = ((lane >> 4) & 1) * 8;

    // stage Q (scaled by 1/8 — exact power of two in fp16) into Ps
    const __half2 qscale = __float2half2_rn(0.125f);
    for (int l = tid; l < 128 * 8; l += 256) {
        int r = l >> 3;
        int c = (l & 7) << 3;
        uint4 v = *(const uint4*)(g_q + base + (size_t)(q0 + r) * ND + c);
        __half2* hp = (__half2*)&v;
        hp[0] = __hmul2(hp[0], qscale);
        hp[1] = __hmul2(hp[1], qscale);
        hp[2] = __hmul2(hp[2], qscale);
        hp[3] = __hmul2(hp[3], qscale);
        *(uint4*)(&Ps[r * FST + c]) = v;
    }
    __syncthreads();

    unsigned qf[4][4];
    #pragma unroll
    for (int ks = 0; ks < 4; ks++) {
        unsigned a = smem_u32(&Ps[(warp * 16 + roff) * FST + ks * 16 + koff]);
        ldsm_x4(qf[ks][0], qf[ks][1], qf[ks][2], qf[ks][3], a);
    }
    __syncthreads();

    float o[8][4];
    #pragma unroll
    for (int nt = 0; nt < 8; nt++)
        #pragma unroll
        for (int c = 0; c < 4; c++) o[nt][c] = 0.0f;
    float m_a = -1e30f, m_b = -1e30f, l_a = 0.0f, l_b = 0.0f;
    const int row_a = q0 + warp * 16 + gid;
    const int row_b = row_a + 8;
    const int nk = 2 * blockIdx.x + 2;

    for (int kt = 0; kt < nk; kt++) {
        const int k0 = kt * 64;

        // load K/V tiles ([kv][d], fp16, direct uint4 copies)
        for (int l = tid; l < 64 * 8; l += 256) {
            int r = l >> 3;
            int c = (l & 7) << 3;
            size_t gidx = base + (size_t)(k0 + r) * ND + c;
            *(uint4*)(&Ks[r * FST + c]) = *(const uint4*)(g_k + gidx);
            *(uint4*)(&Vs[r * FST + c]) = *(const uint4*)(g_v + gidx);
        }
        __syncthreads();

        if (k0 <= q0 + warp * 16 + 15) {
            // S = Q K^T
            float s[8][4];
            #pragma unroll
            for (int nt = 0; nt < 8; nt++)
                #pragma unroll
                for (int c = 0; c < 4; c++) s[nt][c] = 0.0f;

            #pragma unroll
            for (int ks = 0; ks < 4; ks++) {
                unsigned bf[8][2];
                #pragma unroll
                for (int ntp = 0; ntp < 8; ntp += 2) {
                    unsigned a = smem_u32(&Ks[(ntp * 8 + rk + nofl) * FST + ks * 16 + kofl]);
                    ldsm_x4(bf[ntp][0], bf[ntp][1], bf[ntp + 1][0], bf[ntp + 1][1], a);
                }
                #pragma unroll
                for (int nt = 0; nt < 8; nt++)
                    mma_f16(s[nt], qf[ks], bf[nt]);
            }

            // causal mask
            if (k0 + 63 > q0 + warp * 16) {
                #pragma unroll
                for (int nt = 0; nt < 8; nt++) {
                    int kg = k0 + nt * 8 + 2 * tig;
                    if (kg     > row_a) s[nt][0] = -1e30f;
                    if (kg + 1 > row_a) s[nt][1] = -1e30f;
                    if (kg     > row_b) s[nt][2] = -1e30f;
                    if (kg + 1 > row_b) s[nt][3] = -1e30f;
                }
            }

            // online softmax
            float mx_a = -1e30f, mx_b = -1e30f;
            #pragma unroll
            for (int nt = 0; nt < 8; nt++) {
                mx_a = fmaxf(mx_a, fmaxf(s[nt][0], s[nt][1]));
                mx_b = fmaxf(mx_b, fmaxf(s[nt][2], s[nt][3]));
            }
            mx_a = fmaxf(mx_a, __shfl_xor_sync(0xffffffffu, mx_a, 1));
            mx_a = fmaxf(mx_a, __shfl_xor_sync(0xffffffffu, mx_a, 2));
            mx_b = fmaxf(mx_b, __shfl_xor_sync(0xffffffffu, mx_b, 1));
            mx_b = fmaxf(mx_b, __shfl_xor_sync(0xffffffffu, mx_b, 2));

            float mn_a = fmaxf(m_a, mx_a), mn_b = fmaxf(m_b, mx_b);
            float al_a = __expf(m_a - mn_a), al_b = __expf(m_b - mn_b);
            float rs_a = 0.0f, rs_b = 0.0f;
            #pragma unroll
            for (int nt = 0; nt < 8; nt++) {
                s[nt][0] = __expf(s[nt][0] - mn_a);
                s[nt][1] = __expf(s[nt][1] - mn_a);
                s[nt][2] = __expf(s[nt][2] - mn_b);
                s[nt][3] = __expf(s[nt][3] - mn_b);
                rs_a += s[nt][0] + s[nt][1];
                rs_b += s[nt][2] + s[nt][3];
            }
            rs_a += __shfl_xor_sync(0xffffffffu, rs_a, 1);
            rs_a += __shfl_xor_sync(0xffffffffu, rs_a, 2);
            rs_b += __shfl_xor_sync(0xffffffffu, rs_b, 1);
            rs_b += __shfl_xor_sync(0xffffffffu, rs_b, 2);

            l_a = l_a * al_a + rs_a;
            l_b = l_b * al_b + rs_b;
            m_a = mn_a;
            m_b = mn_b;

            #pragma unroll
            for (int nt = 0; nt < 8; nt++) {
                o[nt][0] *= al_a; o[nt][1] *= al_a;
                o[nt][2] *= al_b; o[nt][3] *= al_b;
            }

            // P -> SMEM (fp16), own-warp rows only
            __half2* Pa = (__half2*)&Ps[(warp * 16 + gid) * FST];
            __half2* Pb = (__half2*)&Ps[(warp * 16 + gid + 8) * FST];
            #pragma unroll
            for (int nt = 0; nt < 8; nt++) {
                Pa[nt * 4 + tig] = __floats2half2_rn(s[nt][0], s[nt][1]);
                Pb[nt * 4 + tig] = __floats2half2_rn(s[nt][2], s[nt][3]);
            }
            __syncwarp();

            // O += P V   (V^T via ldmatrix.trans)
            #pragma unroll
            for (int ks = 0; ks < 4; ks++) {
                unsigned af[4];
                {
                    unsigned a = smem_u32(&Ps[(warp * 16 + roff) * FST + ks * 16 + koff]);
                    ldsm_x4(af[0], af[1], af[2], af[3], a);
                }
                unsigned vf[8][2];
                #pragma unroll
                for (int dtp = 0; dtp < 8; dtp += 2) {
                    unsigned a = smem_u32(&Vs[(ks * 16 + rv) * FST + dtp * 8 + dofl]);
                    ldsm_x4_t(vf[dtp][0], vf[dtp][1], vf[dtp + 1][0], vf[dtp + 1][1], a);
                }
                #pragma unroll
                for (int nt = 0; nt < 8; nt++)
                    mma_f16(o[nt], af, vf[nt]);
            }
        }
        __syncthreads();
    }

    // normalize + write O (fp16)
    float ia = 1.0f / l_a, ib = 1.0f / l_b;
    #pragma unroll
    for (int nt = 0; nt < 8; nt++) {
        int d = nt * 8 + 2 * tig;
        *(__half2*)(g_oh + base + (size_t)row_a * ND + d) =
            __floats2half2_rn(o[nt][0] * ia, o[nt][1] * ia);
        *(__half2*)(g_oh + base + (size_t)row_b * ND + d) =
            __floats2half2_rn(o[nt][2] * ib, o[nt][3] * ib);
    }
}

// ---------------------------------------------------------------------------
extern "C" void kernel_launch(void* const* d_in, const int* in_sizes, int n_in,
                              void* d_out, int out_size) {
    const float* x  = (const float*)d_in[0];
    // d_in[1] = mask (bool tril) -- causality is hardcoded
    const float* wq = (const float*)d_in[2];
    const float* wk = (const float*)d_in[3];
    const float* wv = (const float*)d_in[4];
    const float* wo = (const float*)d_in[5];
    float* out = (float*)d_out;

    void *pxh, *pwq, *pwk, *pwv, *pwo, *pq, *pk, *pv, *poh;
    cudaGetSymbolAddress(&pxh, g_xh);
    cudaGetSymbolAddress(&pwq, g_wqh);
    cudaGetSymbolAddress(&pwk, g_wkh);
    cudaGetSymbolAddress(&pwv, g_wvh);
    cudaGetSymbolAddress(&pwo, g_woh);
    cudaGetSymbolAddress(&pq, g_q);
    cudaGetSymbolAddress(&pk, g_k);
    cudaGetSymbolAddress(&pv, g_v);
    cudaGetSymbolAddress(&poh, g_oh);

    rope_table_kernel<<<(NS * 32 + 255) / 256, 256>>>();

    // fp32 -> fp16 input/weight conversion
    cvt_h_kernel<<<(NM * ND / 8 + 255) / 256, 256>>>(x, (__half*)pxh, NM * ND);
    cvt_w_kernel<<<dim3((ND * ND / 8 + 255) / 256, 4), 256>>>(
        wq, wk, wv, wo,
        (__half*)pwq, (__half*)pwk, (__half*)pwv, (__half*)pwo);

    // fused Q/K/V projections (z = 0,1,2; RoPE on z<2), fp16 outputs
    gemm_tc<2, __half><<<dim3(ND / 128, NM / 128, 3), 256>>>(
        (const __half*)pxh, (const __half*)pwq, (const __half*)pwk, (const __half*)pwv,
        (__half*)pq, (__half*)pk, (__half*)pv);

    flash_tc_kernel<<<dim3(NS / 128, NH, NB), 256>>>();

    // output projection: fp16 in, fp32 out
    gemm_tc<0, float><<<dim3(ND / 128, NM / 128, 1), 256>>>(
        (const __half*)poh, (const __half*)pwo, (const __half*)pwo, (const __half*)pwo,
        out, out, out);
}

// round 12
// speedup vs baseline: 1.7503x; 1.0599x over previous
#include <cuda_runtime.h>
#include <cuda_fp16.h>
#include <math.h>

#define NB 4
#define NS 2048
#define ND 1024
#define NH 16
#define NDK 64
#define NM (NB*NS)

// Scratch (device globals: allocation-free rule) — fp16 pipeline
__device__ __half g_xh[(size_t)NM*ND];
__device__ __half g_wqh[(size_t)ND*ND];
__device__ __half g_wkh[(size_t)ND*ND];
__device__ __half g_wvh[(size_t)ND*ND];
__device__ __half g_woh[(size_t)ND*ND];
__device__ __half g_q[(size_t)NM*ND];
__device__ __half g_k[(size_t)NM*ND];
__device__ __half g_v[(size_t)NM*ND];
__device__ __half g_oh[(size_t)NM*ND];
__device__ float  g_cos[NS*(NDK/2)];
__device__ float  g_sin[NS*(NDK/2)];

// ---------------------------------------------------------------------------
// RoPE cos/sin table
// ---------------------------------------------------------------------------
__global__ void rope_table_kernel() {
    int idx = blockIdx.x * blockDim.x + threadIdx.x;
    if (idx >= NS * 32) return;
    int s = idx >> 5;
    int i = idx & 31;
    double freq = exp(-((double)(2 * i) / (double)NDK) * log(10000.0));
    double ang = (double)s * freq;
    g_cos[idx] = (float)cos(ang);
    g_sin[idx] = (float)sin(ang);
}

// ---------------------------------------------------------------------------
// helpers
// ---------------------------------------------------------------------------
__device__ __forceinline__ uint4 pack8h(float4 lo, float4 hi) {
    __half2 h0 = __floats2half2_rn(lo.x, lo.y);
    __half2 h1 = __floats2half2_rn(lo.z, lo.w);
    __half2 h2 = __floats2half2_rn(hi.x, hi.y);
    __half2 h3 = __floats2half2_rn(hi.z, hi.w);
    return make_uint4(*reinterpret_cast<unsigned*>(&h0),
                      *reinterpret_cast<unsigned*>(&h1),
                      *reinterpret_cast<unsigned*>(&h2),
                      *reinterpret_cast<unsigned*>(&h3));
}

__global__ void cvt_h_kernel(const float* __restrict__ src, __half* __restrict__ dst, int n) {
    int i = (blockIdx.x * blockDim.x + threadIdx.x) << 3;
    if (i >= n) return;
    float4 lo = *(const float4*)(src + i);
    float4 hi = *(const float4*)(src + i + 4);
    *(uint4*)(dst + i) = pack8h(lo, hi);
}

__global__ void cvt_w_kernel(const float* __restrict__ w0, const float* __restrict__ w1,
                             const float* __restrict__ w2, const float* __restrict__ w3,
                             __half* __restrict__ d0, __half* __restrict__ d1,
                             __half* __restrict__ d2, __half* __restrict__ d3) {
    const float* src = (blockIdx.y == 0) ? w0 : (blockIdx.y == 1 ? w1 : (blockIdx.y == 2 ? w2 : w3));
    __half*      dst = (blockIdx.y == 0) ? d0 : (blockIdx.y == 1 ? d1 : (blockIdx.y == 2 ? d2 : d3));
    int i = (blockIdx.x * blockDim.x + threadIdx.x) << 3;
    if (i >= ND * ND) return;
    float4 lo = *(const float4*)(src + i);
    float4 hi = *(const float4*)(src + i + 4);
    *(uint4*)(dst + i) = pack8h(lo, hi);
}

__device__ __forceinline__ unsigned smem_u32(const void* p) {
    return (unsigned)__cvta_generic_to_shared(p);
}

__device__ __forceinline__ void ldsm_x4(unsigned& r0, unsigned& r1,
                                        unsigned& r2, unsigned& r3, unsigned a) {
    asm volatile("ldmatrix.sync.aligned.m8n8.x4.shared.b16 {%0,%1,%2,%3}, [%4];"
                 : "=r"(r0), "=r"(r1), "=r"(r2), "=r"(r3) : "r"(a));
}

__device__ __forceinline__ void ldsm_x4_t(unsigned& r0, unsigned& r1,
                                          unsigned& r2, unsigned& r3, unsigned a) {
    asm volatile("ldmatrix.sync.aligned.m8n8.x4.trans.shared.b16 {%0,%1,%2,%3}, [%4];"
                 : "=r"(r0), "=r"(r1), "=r"(r2), "=r"(r3) : "r"(a));
}

__device__ __forceinline__ void mma_f16(float* c, const unsigned* a, const unsigned* b) {
    asm volatile("mma.sync.aligned.m16n8k16.row.col.f32.f16.f16.f32 "
                 "{%0,%1,%2,%3}, {%4,%5,%6,%7}, {%8,%9}, {%0,%1,%2,%3};"
                 : "+f"(c[0]), "+f"(c[1]), "+f"(c[2]), "+f"(c[3])
                 : "r"(a[0]), "r"(a[1]), "r"(a[2]), "r"(a[3]),
                   "r"(b[0]), "r"(b[1]));
}

__device__ __forceinline__ void st2(float* p, float a, float b) {
    *(float2*)p = make_float2(a, b);
}
__device__ __forceinline__ void st2(__half* p, float a, float b) {
    *(__half2*)p = __floats2half2_rn(a, b);
}

// ---------------------------------------------------------------------------
// Tensor-core NT GEMM (fp16 in, fp32 accum): C[m,n] = sum_k A[m,k]*Wt[n,k].
// BM=BN=128, BK=32. 4 warps (128 threads); warp tile 64x64 (2x2 warp grid):
// 8 ldmatrix.x4 per 32 MMAs (0.25 ratio, 33% less shared traffic than 64x32).
// Register prefetch of tile t+1 overlaps compute of tile t (proven R10).
// SMEM row stride 40 halves (80B): ldmatrix conflict-free.
// blockIdx.z selects (W, C) pair; z < NROPE => fused interleaved RoPE.
// ---------------------------------------------------------------------------
#define GKS 40

template<int NROPE, typename TOUT>
__global__ __launch_bounds__(128) void gemm_tc(
    const __half* __restrict__ A,
    const __half* __restrict__ Wa, const __half* __restrict__ Wb, const __half* __restrict__ Wc,
    TOUT* __restrict__ Ca, TOUT* __restrict__ Cb, TOUT* __restrict__ Cc)
{
    const __half* Wt = (blockIdx.z == 0) ? Wa : (blockIdx.z == 1 ? Wb : Wc);
    TOUT*         C  = (blockIdx.z == 0) ? Ca : (blockIdx.z == 1 ? Cb : Cc);
    const int rope   = (int)blockIdx.z < NROPE;

    __shared__ __half As[128 * GKS];
    __shared__ __half Bs[128 * GKS];

    const int tid  = threadIdx.x;
    const int warp = tid >> 5;
    const int lane = tid & 31;
    const int wm   = warp >> 1;      // 0..1
    const int wn   = warp & 1;       // 0..1
    const int gid  = lane >> 2;
    const int tig  = lane & 3;
    const int bm   = blockIdx.y * 128;
    const int bn   = blockIdx.x * 128;

    // loader: 4 threads/row, 8 halves (uint4) each; rows lr+{0,32,64,96}
    const int lr = tid >> 2;         // 0..31
    const int lc = (tid & 3) << 3;
    const __half* Ap = A  + (size_t)(bm + lr) * ND + lc;
    const __half* Wp = Wt + (size_t)(bn + lr) * ND + lc;

    // ldmatrix lane geometry
    const int ra   = (lane & 7) + ((lane >> 3) & 1) * 8;
    const int kaa  = ((lane >> 4) & 1) * 8;
    const int rb   = lane & 7;
    const int kbb  = ((lane >> 3) & 1) * 8;
    const int nbb  = ((lane >> 4) & 1) * 8;

    float acc[4][8][4];
    #pragma unroll
    for (int mt = 0; mt < 4; mt++)
        #pragma unroll
        for (int nt = 0; nt < 8; nt++)
            #pragma unroll
            for (int c = 0; c < 4; c++) acc[mt][nt][c] = 0.0f;

    // prologue: load k-tile 0 into registers
    uint4 rga[4], rgb[4];
    #pragma unroll
    for (int p = 0; p < 4; p++) {
        rga[p] = *(const uint4*)(Ap + (size_t)p * 32 * ND);
        rgb[p] = *(const uint4*)(Wp + (size_t)p * 32 * ND);
    }

    for (int t = 0; t < 32; t++) {
        // store prefetched tile t into SMEM
        #pragma unroll
        for (int p = 0; p < 4; p++) {
            *(uint4*)(&As[(lr + p * 32) * GKS + lc]) = rga[p];
            *(uint4*)(&Bs[(lr + p * 32) * GKS + lc]) = rgb[p];
        }
        __syncthreads();

        // issue LDG for tile t+1 now — latency overlaps the compute below
        if (t < 31) {
            const int k1 = (t + 1) * 32;
            #pragma unroll
            for (int p = 0; p < 4; p++) {
                rga[p] = *(const uint4*)(Ap + (size_t)p * 32 * ND + k1);
                rgb[p] = *(const uint4*)(Wp + (size_t)p * 32 * ND + k1);
            }
        }

        #pragma unroll
        for (int ks = 0; ks < 32; ks += 16) {
            unsigned af[4][4], bf[8][2];
            #pragma unroll
            for (int mt = 0; mt < 4; mt++) {
                unsigned a = smem_u32(&As[(wm * 64 + mt * 16 + ra) * GKS + ks + kaa]);
                ldsm_x4(af[mt][0], af[mt][1], af[mt][2], af[mt][3], a);
            }
            #pragma unroll
            for (int ntp = 0; ntp < 8; ntp += 2) {
                unsigned a = smem_u32(&Bs[(wn * 64 + ntp * 8 + rb + nbb) * GKS + ks + kbb]);
                ldsm_x4(bf[ntp][0], bf[ntp][1], bf[ntp + 1][0], bf[ntp + 1][1], a);
            }
            #pragma unroll
            for (int mt = 0; mt < 4; mt++)
                #pragma unroll
                for (int nt = 0; nt < 8; nt++)
                    mma_f16(acc[mt][nt], af[mt], bf[nt]);
        }
        __syncthreads();
    }

    #pragma unroll
    for (int mt = 0; mt < 4; mt++) {
        int m0 = bm + wm * 64 + mt * 16 + gid;
        #pragma unroll
        for (int nt = 0; nt < 8; nt++) {
            int n = bn + wn * 64 + nt * 8 + 2 * tig;
            float c0 = acc[mt][nt][0], c1 = acc[mt][nt][1];
            float c2 = acc[mt][nt][2], c3 = acc[mt][nt][3];
            if (rope) {
                int ip = (n & 63) >> 1;
                int s0 = m0 & (NS - 1);
                int s1 = (m0 + 8) & (NS - 1);
                float ca = g_cos[s0 * 32 + ip], sa = g_sin[s0 * 32 + ip];
                float cb = g_cos[s1 * 32 + ip], sb = g_sin[s1 * 32 + ip];
                float t0 = c0 * ca - c1 * sa;
                float t1 = c0 * sa + c1 * ca;
                float t2 = c2 * cb - c3 * sb;
                float t3 = c2 * sb + c3 * cb;
                c0 = t0; c1 = t1; c2 = t2; c3 = t3;
            }
            st2(C + (size_t)m0 * ND + n,       c0, c1);
            st2(C + (size_t)(m0 + 8) * ND + n, c2, c3);
        }
    }
}

// ---------------------------------------------------------------------------
// Tensor-core causal flash attention (fp16 mma m16n8k16 + ldmatrix).
// grid = (S/128, H, B), 256 threads (8 warps x 16 q-rows), 64-key tiles.
// Q/K/V fp16 in gmem; O written fp16. Ks/Vs natural [kv][d], stride 72.
// [proven R8 version]
// ---------------------------------------------------------------------------
#define FST 72

__global__ __launch_bounds__(256, 2) void flash_tc_kernel() {
    __shared__ __half Ks[64 * FST];
    __shared__ __half Vs[64 * FST];
    __shared__ __half Ps[128 * FST];

    const int tid  = threadIdx.x;
    const int warp = tid >> 5;
    const int lane = tid & 31;
    const int gid  = lane >> 2;
    const int tig  = lane & 3;
    const int q0   = blockIdx.x * 128;
    const int h    = blockIdx.y;
    const int b    = blockIdx.z;
    const size_t base = (size_t)(b * NS) * ND + (size_t)h * NDK;

    // ldmatrix lane geometry
    const int roff = (lane & 7) + ((lane >> 3) & 1) * 8;
    const int koff = ((lane >> 4) & 1) * 8;
    const int rk   = lane & 7;
    const int kofl = ((lane >> 3) & 1) * 8;
    const int nofl = ((lane >> 4) & 1) * 8;
    const int rv   = (lane & 7) + ((lane >> 3) & 1) * 8;
    const int dofl = ((lane >> 4) & 1) * 8;

    // stage Q (scaled by 1/8 — exact power of two in fp16) into Ps
    const __half2 qscale = __float2half2_rn(0.125f);
    for (int l = tid; l < 128 * 8; l += 256) {
        int r = l >> 3;
        int c = (l & 7) << 3;
        uint4 v = *(const uint4*)(g_q + base + (size_t)(q0 + r) * ND + c);
        __half2* hp = (__half2*)&v;
        hp[0] = __hmul2(hp[0], qscale);
        hp[1] = __hmul2(hp[1], qscale);
        hp[2] = __hmul2(hp[2], qscale);
        hp[3] = __hmul2(hp[3], qscale);
        *(uint4*)(&Ps[r * FST + c]) = v;
    }
    __syncthreads();

    unsigned qf[4][4];
    #pragma unroll
    for (int ks = 0; ks < 4; ks++) {
        unsigned a = smem_u32(&Ps[(warp * 16 + roff) * FST + ks * 16 + koff]);
        ldsm_x4(qf[ks][0], qf[ks][1], qf[ks][2], qf[ks][3], a);
    }
    __syncthreads();

    float o[8][4];
    #pragma unroll
    for (int nt = 0; nt < 8; nt++)
        #pragma unroll
        for (int c = 0; c < 4; c++) o[nt][c] = 0.0f;
    float m_a = -1e30f, m_b = -1e30f, l_a = 0.0f, l_b = 0.0f;
    const int row_a = q0 + warp * 16 + gid;
    const int row_b = row_a + 8;
    const int nk = 2 * blockIdx.x + 2;

    for (int kt = 0; kt < nk; kt++) {
        const int k0 = kt * 64;

        // load K/V tiles ([kv][d], fp16, direct uint4 copies)
        for (int l = tid; l < 64 * 8; l += 256) {
            int r = l >> 3;
            int c = (l & 7) << 3;
            size_t gidx = base + (size_t)(k0 + r) * ND + c;
            *(uint4*)(&Ks[r * FST + c]) = *(const uint4*)(g_k + gidx);
            *(uint4*)(&Vs[r * FST + c]) = *(const uint4*)(g_v + gidx);
        }
        __syncthreads();

        if (k0 <= q0 + warp * 16 + 15) {
            // S = Q K^T
            float s[8][4];
            #pragma unroll
            for (int nt = 0; nt < 8; nt++)
                #pragma unroll
                for (int c = 0; c < 4; c++) s[nt][c] = 0.0f;

            #pragma unroll
            for (int ks = 0; ks < 4; ks++) {
                unsigned bf[8][2];
                #pragma unroll
                for (int ntp = 0; ntp < 8; ntp += 2) {
                    unsigned a = smem_u32(&Ks[(ntp * 8 + rk + nofl) * FST + ks * 16 + kofl]);
                    ldsm_x4(bf[ntp][0], bf[ntp][1], bf[ntp + 1][0], bf[ntp + 1][1], a);
                }
                #pragma unroll
                for (int nt = 0; nt < 8; nt++)
                    mma_f16(s[nt], qf[ks], bf[nt]);
            }

            // causal mask
            if (k0 + 63 > q0 + warp * 16) {
                #pragma unroll
                for (int nt = 0; nt < 8; nt++) {
                    int kg = k0 + nt * 8 + 2 * tig;
                    if (kg     > row_a) s[nt][0] = -1e30f;
                    if (kg + 1 > row_a) s[nt][1] = -1e30f;
                    if (kg     > row_b) s[nt][2] = -1e30f;
                    if (kg + 1 > row_b) s[nt][3] = -1e30f;
                }
            }

            // online softmax
            float mx_a = -1e30f, mx_b = -1e30f;
            #pragma unroll
            for (int nt = 0; nt < 8; nt++) {
                mx_a = fmaxf(mx_a, fmaxf(s[nt][0], s[nt][1]));
                mx_b = fmaxf(mx_b, fmaxf(s[nt][2], s[nt][3]));
            }
            mx_a = fmaxf(mx_a, __shfl_xor_sync(0xffffffffu, mx_a, 1));
            mx_a = fmaxf(mx_a, __shfl_xor_sync(0xffffffffu, mx_a, 2));
            mx_b = fmaxf(mx_b, __shfl_xor_sync(0xffffffffu, mx_b, 1));
            mx_b = fmaxf(mx_b, __shfl_xor_sync(0xffffffffu, mx_b, 2));

            float mn_a = fmaxf(m_a, mx_a), mn_b = fmaxf(m_b, mx_b);
            float al_a = __expf(m_a - mn_a), al_b = __expf(m_b - mn_b);
            float rs_a = 0.0f, rs_b = 0.0f;
            #pragma unroll
            for (int nt = 0; nt < 8; nt++) {
                s[nt][0] = __expf(s[nt][0] - mn_a);
                s[nt][1] = __expf(s[nt][1] - mn_a);
                s[nt][2] = __expf(s[nt][2] - mn_b);
                s[nt][3] = __expf(s[nt][3] - mn_b);
                rs_a += s[nt][0] + s[nt][1];
                rs_b += s[nt][2] + s[nt][3];
            }
            rs_a += __shfl_xor_sync(0xffffffffu, rs_a, 1);
            rs_a += __shfl_xor_sync(0xffffffffu, rs_a, 2);
            rs_b += __shfl_xor_sync(0xffffffffu, rs_b, 1);
            rs_b += __shfl_xor_sync(0xffffffffu, rs_b, 2);

            l_a = l_a * al_a + rs_a;
            l_b = l_b * al_b + rs_b;
            m_a = mn_a;
            m_b = mn_b;

            #pragma unroll
            for (int nt = 0; nt < 8; nt++) {
                o[nt][0] *= al_a; o[nt][1] *= al_a;
                o[nt][2] *= al_b; o[nt][3] *= al_b;
            }

            // P -> SMEM (fp16), own-warp rows only
            __half2* Pa = (__half2*)&Ps[(warp * 16 + gid) * FST];
            __half2* Pb = (__half2*)&Ps[(warp * 16 + gid + 8) * FST];
            #pragma unroll
            for (int nt = 0; nt < 8; nt++) {
                Pa[nt * 4 + tig] = __floats2half2_rn(s[nt][0], s[nt][1]);
                Pb[nt * 4 + tig] = __floats2half2_rn(s[nt][2], s[nt][3]);
            }
            __syncwarp();

            // O += P V   (V^T via ldmatrix.trans)
            #pragma unroll
            for (int ks = 0; ks < 4; ks++) {
                unsigned af[4];
                {
                    unsigned a = smem_u32(&Ps[(warp * 16 + roff) * FST + ks * 16 + koff]);
                    ldsm_x4(af[0], af[1], af[2], af[3], a);
                }
                unsigned vf[8][2];
                #pragma unroll
                for (int dtp = 0; dtp < 8; dtp += 2) {
                    unsigned a = smem_u32(&Vs[(ks * 16 + rv) * FST + dtp * 8 + dofl]);
                    ldsm_x4_t(vf[dtp][0], vf[dtp][1], vf[dtp + 1][0], vf[dtp + 1][1], a);
                }
                #pragma unroll
                for (int nt = 0; nt < 8; nt++)
                    mma_f16(o[nt], af, vf[nt]);
            }
        }
        __syncthreads();
    }

    // normalize + write O (fp16)
    float ia = 1.0f / l_a, ib = 1.0f / l_b;
    #pragma unroll
    for (int nt = 0; nt < 8; nt++) {
        int d = nt * 8 + 2 * tig;
        *(__half2*)(g_oh + base + (size_t)row_a * ND + d) =
            __floats2half2_rn(o[nt][0] * ia, o[nt][1] * ia);
        *(__half2*)(g_oh + base + (size_t)row_b * ND + d) =
            __floats2half2_rn(o[nt][2] * ib, o[nt][3] * ib);
    }
}

// ---------------------------------------------------------------------------
extern "C" void kernel_launch(void* const* d_in, const int* in_sizes, int n_in,
                              void* d_out, int out_size) {
    const float* x  = (const float*)d_in[0];
    // d_in[1] = mask (bool tril) -- causality is hardcoded
    const float* wq = (const float*)d_in[2];
    const float* wk = (const float*)d_in[3];
    const float* wv = (const float*)d_in[4];
    const float* wo = (const float*)d_in[5];
    float* out = (float*)d_out;

    void *pxh, *pwq, *pwk, *pwv, *pwo, *pq, *pk, *pv, *poh;
    cudaGetSymbolAddress(&pxh, g_xh);
    cudaGetSymbolAddress(&pwq, g_wqh);
    cudaGetSymbolAddress(&pwk, g_wkh);
    cudaGetSymbolAddress(&pwv, g_wvh);
    cudaGetSymbolAddress(&pwo, g_woh);
    cudaGetSymbolAddress(&pq, g_q);
    cudaGetSymbolAddress(&pk, g_k);
    cudaGetSymbolAddress(&pv, g_v);
    cudaGetSymbolAddress(&poh, g_oh);

    rope_table_kernel<<<(NS * 32 + 255) / 256, 256>>>();

    // fp32 -> fp16 input/weight conversion
    cvt_h_kernel<<<(NM * ND / 8 + 255) / 256, 256>>>(x, (__half*)pxh, NM * ND);
    cvt_w_kernel<<<dim3((ND * ND / 8 + 255) / 256, 4), 256>>>(
        wq, wk, wv, wo,
        (__half*)pwq, (__half*)pwk, (__half*)pwv, (__half*)pwo);

    // fused Q/K/V projections (z = 0,1,2; RoPE on z<2), fp16 outputs
    gemm_tc<2, __half><<<dim3(ND / 128, NM / 128, 3), 128>>>(
        (const __half*)pxh, (const __half*)pwq, (const __half*)pwk, (const __half*)pwv,
        (__half*)pq, (__half*)pk, (__half*)pv);

    flash_tc_kernel<<<dim3(NS / 128, NH, NB), 256>>>();

    // output projection: fp16 in, fp32 out
    gemm_tc<0, float><<<dim3(ND / 128, NM / 128, 1), 128>>>(
        (const __half*)poh, (const __half*)pwo, (const __half*)pwo, (const __half*)pwo,
        out, out, out);
}